// round 12
// baseline (speedup 1.0000x reference)
#include <cuda_runtime.h>
#include <cstdint>
#include <cstddef>

// Problem dims (fixed by the reference)
#define Bt 1024
#define Tt 512
#define Ii 45
#define Hh 128
#define Oo 45

#define NTH 256          // prepass threads
typedef unsigned long long ull;

// 256 MB scratch: xe[bt][j] = b_ih[j] + b_hh[j] + sum_i x[bt][i]*W_ih[j][i]
__device__ float xe_buf[(size_t)Bt * Tt * Hh];

__device__ __forceinline__ void fma2(ull& acc, ull a, ull b) {
    asm("fma.rn.f32x2 %0, %1, %2, %0;" : "+l"(acc) : "l"(a), "l"(b));
}
__device__ __forceinline__ float2 unpack2(ull d) {
    unsigned lo, hi;
    asm("mov.b64 {%0, %1}, %2;" : "=r"(lo), "=r"(hi) : "l"(d));
    return make_float2(__uint_as_float(lo), __uint_as_float(hi));
}
__device__ __forceinline__ ull pack2f(float lo, float hi) {
    ull d;
    asm("mov.b64 %0, {%1, %2};" : "=l"(d)
        : "r"(__float_as_uint(lo)), "r"(__float_as_uint(hi)));
    return d;
}

// tanh(x) = 1 - 2/(exp(2x)+1): ~1e-6 abs err, exact +/-1 saturation.
__device__ __forceinline__ float fast_tanh(float x) {
    float e = __expf(2.0f * x);
    return 1.0f - __fdividef(2.0f, e + 1.0f);
}

// ============================================================================
// Pre-pass (unchanged from R11, measured ~225 us)
// ============================================================================
__global__ void __launch_bounds__(NTH, 2)
xe_prepass_kernel(const float* __restrict__ x,
                  const float* __restrict__ W_ih,
                  const float* __restrict__ b_ih,
                  const float* __restrict__ b_hh)
{
    __shared__ float xs[128 * 48];
    __shared__ ull   wp2[24 * 128];

    const int tid = threadIdx.x;
    const int jp  = tid & 63, btg = tid >> 6;
    const int j0  = 2 * jp, j1 = j0 + 1;
    const size_t btBase = (size_t)blockIdx.x * 128;

    for (int idx = tid; idx < 128 * 48; idx += NTH) {
        const int btl = idx / 48, ii = idx - btl * 48;
        xs[idx] = (ii < Ii) ? x[(btBase + btl) * Ii + ii] : 0.0f;
    }
    for (int idx = tid; idx < 128 * 24; idx += NTH) {
        const int jj = idx / 24, p = idx - jj * 24;
        const int ia = 2 * p, ib = ia + 1;
        const float w0 = (ia < Ii) ? W_ih[jj * Ii + ia] : 0.0f;
        const float w1 = (ib < Ii) ? W_ih[jj * Ii + ib] : 0.0f;
        wp2[p * 128 + jj] = pack2f(w0, w1);
    }
    const float bi0 = b_ih[j0] + b_hh[j0];
    const float bi1 = b_ih[j1] + b_hh[j1];
    __syncthreads();

    ull wA[24], wB[24];
    #pragma unroll
    for (int p = 0; p < 24; ++p) {
        wA[p] = wp2[p * 128 + j0];
        wB[p] = wp2[p * 128 + j1];
    }

    for (int c = 0; c < 8; ++c) {
        const int bt0 = btg * 32 + c * 4;
        ull aA[4] = {0ull, 0ull, 0ull, 0ull};
        ull aB[4] = {0ull, 0ull, 0ull, 0ull};

        #pragma unroll
        for (int q = 0; q < 12; ++q) {
            #pragma unroll
            for (int r = 0; r < 4; ++r) {
                const ulonglong2 v = *reinterpret_cast<const ulonglong2*>(
                    xs + (bt0 + r) * 48 + q * 4);
                fma2(aA[r], wA[2 * q], v.x); fma2(aA[r], wA[2 * q + 1], v.y);
                fma2(aB[r], wB[2 * q], v.x); fma2(aB[r], wB[2 * q + 1], v.y);
            }
        }
        #pragma unroll
        for (int r = 0; r < 4; ++r) {
            const float2 fA = unpack2(aA[r]);
            const float2 fB = unpack2(aB[r]);
            float2 o;
            o.x = bi0 + fA.x + fA.y;
            o.y = bi1 + fB.x + fB.y;
            *reinterpret_cast<float2*>(
                xe_buf + (btBase + bt0 + r) * Hh + j0) = o;
        }
    }
}

// ============================================================================
// Recurrence v3: full-k per thread, NO reduction, ONE barrier per step.
// Grid 342 CTAs x 128 thr; thread tid owns hidden unit j = tid (full k=128
// weights in 64 ull registers) and computes 3 batch rows completely.
// ============================================================================
#define LNB   3
#define LNBLK 342      // ceil(1024/3)

__global__ void __launch_bounds__(128, 3)
rnn_loop_kernel(const float* __restrict__ W_hh,
                const float* __restrict__ W_fc,
                const float* __restrict__ b_fc,
                float* __restrict__ out)
{
    __shared__ float hT[2 * LNB * Hh];       // [buf][row][k]   3 KB
    __shared__ float wstage[32 * 130];       // 32-row staging, pad 130  16.6 KB

    const int tid = threadIdx.x;
    const int j   = tid;                     // hidden unit owned
    const int rowBase = blockIdx.x * LNB;

    for (int idx = tid; idx < 2 * LNB * Hh; idx += 128) hT[idx] = 0.0f;

    // ---- Load full W_hh row j into 64 ull registers, via SMEM chunks ----
    ull wk[64];
    #pragma unroll 1
    for (int c = 0; c < 4; ++c) {
        __syncthreads();
        // stage rows [32c, 32c+32) coalesced: 4096 elems / 128 thr = 32 iters
        #pragma unroll 1
        for (int it = 0; it < 32; ++it) {
            const int idx = tid + it * 128;
            const int r = idx >> 7, col = idx & 127;
            wstage[r * 130 + col] = W_hh[(32 * c + r) * Hh + col];
        }
        __syncthreads();
        if ((j >> 5) == c) {
            const float* wr = wstage + (j & 31) * 130;
            #pragma unroll
            for (int q = 0; q < 64; ++q)
                wk[q] = *reinterpret_cast<const ull*>(wr + 2 * q);
        }
    }

    // ---- xe streams for this thread's 3 rows (clamped for pad rows) ----
    const int r0c = (rowBase + 0 < Bt) ? rowBase + 0 : Bt - 1;
    const int r1c = (rowBase + 1 < Bt) ? rowBase + 1 : Bt - 1;
    const int r2c = (rowBase + 2 < Bt) ? rowBase + 2 : Bt - 1;
    const float* xp0 = xe_buf + ((size_t)r0c * Tt) * Hh + j;
    const float* xp1 = xe_buf + ((size_t)r1c * Tt) * Hh + j;
    const float* xp2 = xe_buf + ((size_t)r2c * Tt) * Hh + j;
    float xe0 = xp0[0], xe1 = xp1[0], xe2 = xp2[0];   // t = 0

    __syncthreads();

    for (int t = 0; t < Tt; ++t) {
        const int cur = t & 1;
        const float* hc = hT + cur * (LNB * Hh);

        // Prefetch next step's xe (3 coalesced LDGs, hidden behind FMAs)
        float n0 = 0.0f, n1 = 0.0f, n2 = 0.0f;
        if (t + 1 < Tt) {
            const size_t off = (size_t)(t + 1) * Hh;
            n0 = xp0[off]; n1 = xp1[off]; n2 = xp2[off];
        }

        // Complete pre-activation for (j, rows 0..2): no reduction needed
        ull a0 = 0ull, a1 = 0ull, a2 = 0ull;
        #pragma unroll
        for (int q = 0; q < 32; ++q) {          // 32 LDS.128 per row
            const ull w0 = wk[2 * q], w1 = wk[2 * q + 1];
            ulonglong2 v;
            v = *reinterpret_cast<const ulonglong2*>(hc + 0 * Hh + q * 4);
            fma2(a0, w0, v.x); fma2(a0, w1, v.y);
            v = *reinterpret_cast<const ulonglong2*>(hc + 1 * Hh + q * 4);
            fma2(a1, w0, v.x); fma2(a1, w1, v.y);
            v = *reinterpret_cast<const ulonglong2*>(hc + 2 * Hh + q * 4);
            fma2(a2, w0, v.x); fma2(a2, w1, v.y);
        }

        // tanh + write h_new for all 3 rows (thread owns column j outright)
        float* hn = hT + (cur ^ 1) * (LNB * Hh);
        const float2 f0 = unpack2(a0);
        const float2 f1 = unpack2(a1);
        const float2 f2 = unpack2(a2);
        hn[0 * Hh + j] = fast_tanh(f0.x + f0.y + xe0);
        hn[1 * Hh + j] = fast_tanh(f1.x + f1.y + xe1);
        hn[2 * Hh + j] = fast_tanh(f2.x + f2.y + xe2);
        xe0 = n0; xe1 = n1; xe2 = n2;

        __syncthreads();   // single barrier per step
    }

    // ---- Final FC: out[b][o] = b_fc[o] + sum_j W_fc[o][j] * h_last[b][j] ----
    // Tt even -> last h landed in buffer 0. Layout [row][j].
    const int nr = (Bt - rowBase < LNB) ? (Bt - rowBase) : LNB;
    const float* hlast = hT;
    for (int idx = tid; idx < nr * Oo; idx += 128) {
        const int b = idx / Oo;
        const int o = idx - b * Oo;
        float s = b_fc[o];
        const float* wp = W_fc + o * Hh;
        const float* hp = hlast + b * Hh;
        #pragma unroll 8
        for (int jj = 0; jj < Hh; ++jj)
            s = fmaf(wp[jj], hp[jj], s);
        out[(rowBase + b) * Oo + o] = s;
    }
}

extern "C" void kernel_launch(void* const* d_in, const int* in_sizes, int n_in,
                              void* d_out, int out_size)
{
    const float* x   = (const float*)d_in[0];
    const float* Wih = (const float*)d_in[1];
    const float* bih = (const float*)d_in[2];
    const float* Whh = (const float*)d_in[3];
    const float* bhh = (const float*)d_in[4];
    const float* Wfc = (const float*)d_in[5];
    const float* bfc = (const float*)d_in[6];
    float* out = (float*)d_out;

    xe_prepass_kernel<<<4096, NTH>>>(x, Wih, bih, bhh);
    rnn_loop_kernel<<<LNBLK, 128>>>(Whh, Wfc, bfc, out);
}

// round 13
// speedup vs baseline: 1.2307x; 1.2307x over previous
#include <cuda_runtime.h>
#include <cstdint>
#include <cstddef>

// Problem dims (fixed by the reference)
#define Bt 1024
#define Tt 512
#define Ii 45
#define Hh 128
#define Oo 45

#define NTH 256
#define NBMAX 4
typedef unsigned long long ull;

// 256 MB scratch: xe[bt][j] = b_ih[j] + b_hh[j] + sum_i x[bt][i]*W_ih[j][i]
__device__ float xe_buf[(size_t)Bt * Tt * Hh];

__device__ __forceinline__ void fma2(ull& acc, ull a, ull b) {
    asm("fma.rn.f32x2 %0, %1, %2, %0;" : "+l"(acc) : "l"(a), "l"(b));
}
__device__ __forceinline__ void add2(ull& acc, ull a) {
    asm("add.rn.f32x2 %0, %0, %1;" : "+l"(acc) : "l"(a));
}
__device__ __forceinline__ float2 unpack2(ull d) {
    unsigned lo, hi;
    asm("mov.b64 {%0, %1}, %2;" : "=r"(lo), "=r"(hi) : "l"(d));
    return make_float2(__uint_as_float(lo), __uint_as_float(hi));
}
__device__ __forceinline__ ull pack2f(float lo, float hi) {
    ull d;
    asm("mov.b64 %0, {%1, %2};" : "=l"(d)
        : "r"(__float_as_uint(lo)), "r"(__float_as_uint(hi)));
    return d;
}

// tanh(x) = 1 - 2/(exp(2x)+1): ~1e-6 abs err, exact +/-1 saturation.
__device__ __forceinline__ float fast_tanh(float x) {
    float e = __expf(2.0f * x);
    return 1.0f - __fdividef(2.0f, e + 1.0f);
}

// ============================================================================
// Pre-pass (unchanged from R11, measured ~225 us)
// ============================================================================
__global__ void __launch_bounds__(NTH, 2)
xe_prepass_kernel(const float* __restrict__ x,
                  const float* __restrict__ W_ih,
                  const float* __restrict__ b_ih,
                  const float* __restrict__ b_hh)
{
    __shared__ float xs[128 * 48];
    __shared__ ull   wp2[24 * 128];

    const int tid = threadIdx.x;
    const int jp  = tid & 63, btg = tid >> 6;
    const int j0  = 2 * jp, j1 = j0 + 1;
    const size_t btBase = (size_t)blockIdx.x * 128;

    for (int idx = tid; idx < 128 * 48; idx += NTH) {
        const int btl = idx / 48, ii = idx - btl * 48;
        xs[idx] = (ii < Ii) ? x[(btBase + btl) * Ii + ii] : 0.0f;
    }
    for (int idx = tid; idx < 128 * 24; idx += NTH) {
        const int jj = idx / 24, p = idx - jj * 24;
        const int ia = 2 * p, ib = ia + 1;
        const float w0 = (ia < Ii) ? W_ih[jj * Ii + ia] : 0.0f;
        const float w1 = (ib < Ii) ? W_ih[jj * Ii + ib] : 0.0f;
        wp2[p * 128 + jj] = pack2f(w0, w1);
    }
    const float bi0 = b_ih[j0] + b_hh[j0];
    const float bi1 = b_ih[j1] + b_hh[j1];
    __syncthreads();

    ull wA[24], wB[24];
    #pragma unroll
    for (int p = 0; p < 24; ++p) {
        wA[p] = wp2[p * 128 + j0];
        wB[p] = wp2[p * 128 + j1];
    }

    for (int c = 0; c < 8; ++c) {
        const int bt0 = btg * 32 + c * 4;
        ull aA[4] = {0ull, 0ull, 0ull, 0ull};
        ull aB[4] = {0ull, 0ull, 0ull, 0ull};

        #pragma unroll
        for (int q = 0; q < 12; ++q) {
            #pragma unroll
            for (int r = 0; r < 4; ++r) {
                const ulonglong2 v = *reinterpret_cast<const ulonglong2*>(
                    xs + (bt0 + r) * 48 + q * 4);
                fma2(aA[r], wA[2 * q], v.x); fma2(aA[r], wA[2 * q + 1], v.y);
                fma2(aB[r], wB[2 * q], v.x); fma2(aB[r], wB[2 * q + 1], v.y);
            }
        }
        #pragma unroll
        for (int r = 0; r < 4; ++r) {
            const float2 fA = unpack2(aA[r]);
            const float2 fB = unpack2(aB[r]);
            float2 o;
            o.x = bi0 + fA.x + fA.y;
            o.y = bi1 + fB.x + fB.y;
            *reinterpret_cast<float2*>(
                xe_buf + (btBase + bt0 + r) * Hh + j0) = o;
        }
    }
}

// ============================================================================
// Recurrence loop, R11 structure templated on NB (3 or 4 rows per CTA).
// Grid 296 = 2 CTAs/SM; 136 four-row + 160 three-row CTAs arranged so the
// (b, b+148) wave pairing puts 4+3 = 7 rows on each SM (was 8 padded).
// ============================================================================
template <int NB>
__device__ __forceinline__ void rnn_loop_body(
    int rowStart,
    const float* __restrict__ W_hh,
    const float* __restrict__ W_fc,
    const float* __restrict__ b_fc,
    float* __restrict__ out,
    float* hT, ull* part)
{
    const int tid = threadIdx.x;
    const int jp  = tid & 63;       // j pair: j0 = 2jp, j1 = 2jp+1
    const int qt  = tid >> 6;       // k quarter [32qt, 32qt+32)
    const int j0  = 2 * jp, j1 = 2 * jp + 1;

    for (int idx = tid; idx < 2 * NBMAX * Hh; idx += NTH) hT[idx] = 0.0f;

    // W_hh rows j0/j1, k slice, straight from GMEM (L2-broadcast, one-time)
    ull wkA[16], wkB[16];
    {
        const float* wa = W_hh + j0 * Hh + qt * 32;
        const float* wb = W_hh + j1 * Hh + qt * 32;
        #pragma unroll
        for (int q = 0; q < 16; ++q) {
            wkA[q] = *reinterpret_cast<const ull*>(wa + 2 * q);
            wkB[q] = *reinterpret_cast<const ull*>(wb + 2 * q);
        }
    }

    // This thread finishes row qt (if qt < NB); its xe stream
    const bool fin = (qt < NB);
    const int myRow = fin ? (rowStart + qt) : rowStart;
    const float* xe_p = xe_buf + ((size_t)myRow * Tt) * Hh + j0;
    float2 xe_cur = *reinterpret_cast<const float2*>(xe_p);   // t = 0

    __syncthreads();

    for (int t = 0; t < Tt; ++t) {
        const int cur = t & 1;
        const float* hc = hT + cur * (NBMAX * Hh) + qt * 32;

        // Prefetch next step's xe (hidden behind the FMA loop)
        float2 xe_nxt = make_float2(0.0f, 0.0f);
        if (t + 1 < Tt)
            xe_nxt = *reinterpret_cast<const float2*>(xe_p + (size_t)(t + 1) * Hh);

        // Packed accumulators per (j, row): lanes = (even-k, odd-k) partials
        ull aA[NB], aB[NB];
        #pragma unroll
        for (int r = 0; r < NB; ++r) { aA[r] = 0ull; aB[r] = 0ull; }

        // Recurrent contribution: 8 k-quads; each broadcast LDS.128 feeds 4 fma2
        #pragma unroll
        for (int q = 0; q < 8; ++q) {
            const ull wA0 = wkA[2 * q], wA1 = wkA[2 * q + 1];
            const ull wB0 = wkB[2 * q], wB1 = wkB[2 * q + 1];
            #pragma unroll
            for (int r = 0; r < NB; ++r) {
                const ulonglong2 v =
                    *reinterpret_cast<const ulonglong2*>(hc + r * Hh + q * 4);
                fma2(aA[r], wA0, v.x); fma2(aA[r], wA1, v.y);
                fma2(aB[r], wB0, v.x); fma2(aB[r], wB1, v.y);
            }
        }

        // Post partials (16B STS) for rows this quarter does not finish
        ull* myp = part + (qt * NBMAX) * Hh + j0;
        #pragma unroll
        for (int r = 0; r < NB; ++r) {
            if (r != qt) {
                ulonglong2 v; v.x = aA[r]; v.y = aB[r];
                *reinterpret_cast<ulonglong2*>(myp + r * Hh) = v;
            }
        }
        __syncthreads();

        // Finish row r == qt: sum quarters, add xe (bias folded in), tanh
        if (fin) {
            const int r = qt;
            ull sA = aA[r], sB = aB[r];
            #pragma unroll
            for (int qq = 0; qq < 4; ++qq) {
                if (qq != qt) {
                    const ulonglong2 p = *reinterpret_cast<const ulonglong2*>(
                        part + (qq * NBMAX + r) * Hh + j0);
                    add2(sA, p.x);
                    add2(sB, p.y);
                }
            }
            const float2 fA = unpack2(sA);
            const float2 fB = unpack2(sB);
            float2 o;
            o.x = fast_tanh(fA.x + fA.y + xe_cur.x);
            o.y = fast_tanh(fB.x + fB.y + xe_cur.y);
            float* hn = hT + (cur ^ 1) * (NBMAX * Hh);
            *reinterpret_cast<float2*>(hn + r * Hh + j0) = o;
        }
        xe_cur = xe_nxt;

        __syncthreads();
    }

    // ---- Final FC: out[b][o] = b_fc[o] + sum_j W_fc[o][j] * h_last[b][j] ----
    // Tt even -> last h landed in buffer 0. Layout [row][j].
    const float* hlast = hT;
    if (tid < NB * Oo) {
        const int b = tid / Oo;
        const int o = tid - b * Oo;
        float s = b_fc[o];
        const float* wp = W_fc + o * Hh;
        const float* hp = hlast + b * Hh;
        #pragma unroll 8
        for (int jj = 0; jj < Hh; ++jj)
            s = fmaf(wp[jj], hp[jj], s);
        out[(rowStart + b) * Oo + o] = s;
    }
}

#define LNBLK 296   // 2x148; safe on 148- or 152-SM parts

__global__ void __launch_bounds__(NTH, 2)
rnn_loop_kernel(const float* __restrict__ W_hh,
                const float* __restrict__ W_fc,
                const float* __restrict__ b_fc,
                float* __restrict__ out)
{
    __shared__ float sm[2 * NBMAX * Hh + 4 * NBMAX * Hh * 2];  // 20 KB
    float* hT  = sm;
    ull*  part = reinterpret_cast<ull*>(sm + 2 * NBMAX * Hh);

    const int bid = blockIdx.x;
    // Row layout: bids [0,136) -> 4 rows; [136,148) -> 3; [148,296) -> 3.
    // Wave pairing (b, b+148): 4-row CTAs pair with 3-row CTAs -> 7 rows/SM.
    if (bid < 136) {
        rnn_loop_body<4>(4 * bid, W_hh, W_fc, b_fc, out, hT, part);
    } else if (bid < 148) {
        rnn_loop_body<3>(544 + 3 * (bid - 136), W_hh, W_fc, b_fc, out, hT, part);
    } else {
        rnn_loop_body<3>(580 + 3 * (bid - 148), W_hh, W_fc, b_fc, out, hT, part);
    }
}

extern "C" void kernel_launch(void* const* d_in, const int* in_sizes, int n_in,
                              void* d_out, int out_size)
{
    const float* x   = (const float*)d_in[0];
    const float* Wih = (const float*)d_in[1];
    const float* bih = (const float*)d_in[2];
    const float* Whh = (const float*)d_in[3];
    const float* bhh = (const float*)d_in[4];
    const float* Wfc = (const float*)d_in[5];
    const float* bfc = (const float*)d_in[6];
    float* out = (float*)d_out;

    xe_prepass_kernel<<<4096, NTH>>>(x, Wih, bih, bhh);
    rnn_loop_kernel<<<LNBLK, NTH>>>(Whh, Wfc, bfc, out);
}

// round 14
// speedup vs baseline: 1.4281x; 1.1604x over previous
#include <cuda_runtime.h>
#include <cstdint>
#include <cstddef>

// Problem dims (fixed by the reference)
#define Bt 1024
#define Tt 512
#define Ii 45
#define Hh 128
#define Oo 45

#define NTH 256
#define NBMAX 4
typedef unsigned long long ull;

// 256 MB scratch: xe[bt][j] = b_ih[j] + b_hh[j] + sum_i x[bt][i]*W_ih[j][i]
__device__ float xe_buf[(size_t)Bt * Tt * Hh];

__device__ __forceinline__ void fma2(ull& acc, ull a, ull b) {
    asm("fma.rn.f32x2 %0, %1, %2, %0;" : "+l"(acc) : "l"(a), "l"(b));
}
__device__ __forceinline__ float2 unpack2(ull d) {
    unsigned lo, hi;
    asm("mov.b64 {%0, %1}, %2;" : "=r"(lo), "=r"(hi) : "l"(d));
    return make_float2(__uint_as_float(lo), __uint_as_float(hi));
}
__device__ __forceinline__ ull pack2f(float lo, float hi) {
    ull d;
    asm("mov.b64 %0, {%1, %2};" : "=l"(d)
        : "r"(__float_as_uint(lo)), "r"(__float_as_uint(hi)));
    return d;
}

// tanh(x) = 1 - 2/(exp(2x)+1): ~1e-6 abs err, exact +/-1 saturation.
__device__ __forceinline__ float fast_tanh(float x) {
    float e = __expf(2.0f * x);
    return 1.0f - __fdividef(2.0f, e + 1.0f);
}

// ============================================================================
// Pre-pass (unchanged; measured ~95-225 us, near floor)
// ============================================================================
__global__ void __launch_bounds__(NTH, 2)
xe_prepass_kernel(const float* __restrict__ x,
                  const float* __restrict__ W_ih,
                  const float* __restrict__ b_ih,
                  const float* __restrict__ b_hh)
{
    __shared__ float xs[128 * 48];
    __shared__ ull   wp2[24 * 128];

    const int tid = threadIdx.x;
    const int jp  = tid & 63, btg = tid >> 6;
    const int j0  = 2 * jp, j1 = j0 + 1;
    const size_t btBase = (size_t)blockIdx.x * 128;

    for (int idx = tid; idx < 128 * 48; idx += NTH) {
        const int btl = idx / 48, ii = idx - btl * 48;
        xs[idx] = (ii < Ii) ? x[(btBase + btl) * Ii + ii] : 0.0f;
    }
    for (int idx = tid; idx < 128 * 24; idx += NTH) {
        const int jj = idx / 24, p = idx - jj * 24;
        const int ia = 2 * p, ib = ia + 1;
        const float w0 = (ia < Ii) ? W_ih[jj * Ii + ia] : 0.0f;
        const float w1 = (ib < Ii) ? W_ih[jj * Ii + ib] : 0.0f;
        wp2[p * 128 + jj] = pack2f(w0, w1);
    }
    const float bi0 = b_ih[j0] + b_hh[j0];
    const float bi1 = b_ih[j1] + b_hh[j1];
    __syncthreads();

    ull wA[24], wB[24];
    #pragma unroll
    for (int p = 0; p < 24; ++p) {
        wA[p] = wp2[p * 128 + j0];
        wB[p] = wp2[p * 128 + j1];
    }

    for (int c = 0; c < 8; ++c) {
        const int bt0 = btg * 32 + c * 4;
        ull aA[4] = {0ull, 0ull, 0ull, 0ull};
        ull aB[4] = {0ull, 0ull, 0ull, 0ull};

        #pragma unroll
        for (int q = 0; q < 12; ++q) {
            #pragma unroll
            for (int r = 0; r < 4; ++r) {
                const ulonglong2 v = *reinterpret_cast<const ulonglong2*>(
                    xs + (bt0 + r) * 48 + q * 4);
                fma2(aA[r], wA[2 * q], v.x); fma2(aA[r], wA[2 * q + 1], v.y);
                fma2(aB[r], wB[2 * q], v.x); fma2(aB[r], wB[2 * q + 1], v.y);
            }
        }
        #pragma unroll
        for (int r = 0; r < 4; ++r) {
            const float2 fA = unpack2(aA[r]);
            const float2 fB = unpack2(aB[r]);
            float2 o;
            o.x = bi0 + fA.x + fA.y;
            o.y = bi1 + fB.x + fB.y;
            *reinterpret_cast<float2*>(
                xe_buf + (btBase + bt0 + r) * Hh + j0) = o;
        }
    }
}

// ============================================================================
// Recurrence loop v4: 4 j per thread -> each broadcast LDS.128 feeds 8 fma2.
// lane jq owns j{4jq..4jq+3}; warp g owns k slice [16g, 16g+16).
// Partials collapsed to scalar float4 before posting (1 STS.128 per row).
// Grid 296: 136 four-row + 160 three-row CTAs (7 rows per SM).
// ============================================================================
template <int NB>
__device__ __forceinline__ void rnn_loop_body(
    int rowStart,
    const float* __restrict__ W_hh,
    const float* __restrict__ W_fc,
    const float* __restrict__ b_fc,
    float* __restrict__ out,
    float* hT, float* part)
{
    const int tid = threadIdx.x;
    const int jq  = tid & 31;       // lane -> j quad
    const int grp = tid >> 5;       // warp -> k slice [16*grp, 16*grp+16)
    const int j0  = 4 * jq;

    for (int idx = tid; idx < 2 * NBMAX * Hh; idx += NTH) hT[idx] = 0.0f;

    // Weights: 4 j rows x 16 k, packed over k (one-time strided LDG, tiny)
    ull wk[4][8];
    #pragma unroll
    for (int jj = 0; jj < 4; ++jj) {
        const float* wr = W_hh + (j0 + jj) * Hh + grp * 16;
        #pragma unroll
        for (int p = 0; p < 8; ++p)
            wk[jj][p] = *reinterpret_cast<const ull*>(wr + 2 * p);
    }

    // Warp grp finishes row grp (if grp < NB)
    const bool fin = (grp < NB);
    const int myRow = fin ? (rowStart + grp) : rowStart;
    const float* xe_p = xe_buf + ((size_t)myRow * Tt) * Hh + j0;
    float4 xe_cur = make_float4(0.f, 0.f, 0.f, 0.f);
    if (fin) xe_cur = *reinterpret_cast<const float4*>(xe_p);

    __syncthreads();

    for (int t = 0; t < Tt; ++t) {
        const int cur = t & 1;
        const float* hc = hT + cur * (NBMAX * Hh) + grp * 16;

        // Prefetch next step's xe (finishing warps only; hidden behind FMAs)
        float4 xe_nxt = make_float4(0.f, 0.f, 0.f, 0.f);
        if (fin && t + 1 < Tt)
            xe_nxt = *reinterpret_cast<const float4*>(xe_p + (size_t)(t + 1) * Hh);

        // acc[jj][r]: packed (even-k, odd-k) partial sums
        ull acc[4][NB];
        #pragma unroll
        for (int jj = 0; jj < 4; ++jj)
            #pragma unroll
            for (int r = 0; r < NB; ++r) acc[jj][r] = 0ull;

        // Inner: 4 k-quads x NB rows; each broadcast LDS.128 feeds 8 fma2
        #pragma unroll
        for (int q = 0; q < 4; ++q) {
            #pragma unroll
            for (int r = 0; r < NB; ++r) {
                const ulonglong2 v =
                    *reinterpret_cast<const ulonglong2*>(hc + r * Hh + q * 4);
                #pragma unroll
                for (int jj = 0; jj < 4; ++jj) {
                    fma2(acc[jj][r], wk[jj][2 * q], v.x);
                    fma2(acc[jj][r], wk[jj][2 * q + 1], v.y);
                }
            }
        }

        // Collapse packed lanes to scalars; post float4 partials (not own row)
        float4 own = make_float4(0.f, 0.f, 0.f, 0.f);
        #pragma unroll
        for (int r = 0; r < NB; ++r) {
            float4 s;
            { const float2 f = unpack2(acc[0][r]); s.x = f.x + f.y; }
            { const float2 f = unpack2(acc[1][r]); s.y = f.x + f.y; }
            { const float2 f = unpack2(acc[2][r]); s.z = f.x + f.y; }
            { const float2 f = unpack2(acc[3][r]); s.w = f.x + f.y; }
            if (r == grp) own = s;
            else *reinterpret_cast<float4*>(part + (grp * NBMAX + r) * Hh + j0) = s;
        }
        __syncthreads();

        // Finish row grp: add 7 other groups' partials + xe, tanh, store h
        if (fin) {
            const int r = grp;
            float4 s = own;
            #pragma unroll
            for (int g = 0; g < 8; ++g) {
                if (g != grp) {
                    const float4 p = *reinterpret_cast<const float4*>(
                        part + (g * NBMAX + r) * Hh + j0);
                    s.x += p.x; s.y += p.y; s.z += p.z; s.w += p.w;
                }
            }
            float4 o;
            o.x = fast_tanh(s.x + xe_cur.x);
            o.y = fast_tanh(s.y + xe_cur.y);
            o.z = fast_tanh(s.z + xe_cur.z);
            o.w = fast_tanh(s.w + xe_cur.w);
            float* hn = hT + (cur ^ 1) * (NBMAX * Hh) + r * Hh + j0;
            *reinterpret_cast<float4*>(hn) = o;
        }
        xe_cur = xe_nxt;

        __syncthreads();
    }

    // ---- Final FC: out[b][o] = b_fc[o] + sum_j W_fc[o][j] * h_last[b][j] ----
    // Tt even -> last h landed in buffer 0. Layout [row][j].
    const float* hlast = hT;
    if (tid < NB * Oo) {
        const int b = tid / Oo;
        const int o = tid - b * Oo;
        float s = b_fc[o];
        const float* wp = W_fc + o * Hh;
        const float* hp = hlast + b * Hh;
        #pragma unroll 8
        for (int jj = 0; jj < Hh; ++jj)
            s = fmaf(wp[jj], hp[jj], s);
        out[(rowStart + b) * Oo + o] = s;
    }
}

#define LNBLK 296   // 2x148; 4-row CTAs pair with 3-row CTAs -> 7 rows/SM

__global__ void __launch_bounds__(NTH, 2)
rnn_loop_kernel(const float* __restrict__ W_hh,
                const float* __restrict__ W_fc,
                const float* __restrict__ b_fc,
                float* __restrict__ out)
{
    __shared__ float sm[2 * NBMAX * Hh + 8 * NBMAX * Hh];  // hT 4KB + part 16KB
    float* hT   = sm;
    float* part = sm + 2 * NBMAX * Hh;

    const int bid = blockIdx.x;
    if (bid < 136) {
        rnn_loop_body<4>(4 * bid, W_hh, W_fc, b_fc, out, hT, part);
    } else if (bid < 148) {
        rnn_loop_body<3>(544 + 3 * (bid - 136), W_hh, W_fc, b_fc, out, hT, part);
    } else {
        rnn_loop_body<3>(580 + 3 * (bid - 148), W_hh, W_fc, b_fc, out, hT, part);
    }
}

extern "C" void kernel_launch(void* const* d_in, const int* in_sizes, int n_in,
                              void* d_out, int out_size)
{
    const float* x   = (const float*)d_in[0];
    const float* Wih = (const float*)d_in[1];
    const float* bih = (const float*)d_in[2];
    const float* Whh = (const float*)d_in[3];
    const float* bhh = (const float*)d_in[4];
    const float* Wfc = (const float*)d_in[5];
    const float* bfc = (const float*)d_in[6];
    float* out = (float*)d_out;

    xe_prepass_kernel<<<4096, NTH>>>(x, Wih, bih, bhh);
    rnn_loop_kernel<<<LNBLK, NTH>>>(Whh, Wfc, bfc, out);
}